// round 8
// baseline (speedup 1.0000x reference)
#include <cuda_runtime.h>
#include <math.h>

// HawkesPointProcess: B=8, N=4096. One CTA per batch row, 512 threads,
// 8 elements/thread. Shuffle affine scan, 3 barriers total, single-log trick.
//
//   A_i = e_i*(A_{i-1}+1), e_i = exp(-beta*(t_i - t_{i-1})), e_0 := 0
//   lamb_i = A_i*alpha*beta + mu
//   out[b] = sum_i log(lamb_i+1e-8)*m_i
//            - [ (t1-t0)*mu - alpha*( sum_i exp(-beta*(t1-t_i)*m_i + (1-m_i)*(-1e20)) - sum_i m_i ) ]

#define NT 512
#define NW (NT / 32)   // 16 warps
#define CHUNK 8        // NT*CHUNK == N == 4096

__device__ __forceinline__ float softplus_fast(float x) {
    return __logf(1.0f + __expf(x));   // |x| ~ 0.3 -> rel err ~1e-6
}

__global__ __launch_bounds__(NT, 1)
void hawkes_kernel(const float* __restrict__ et,
                   const float* __restrict__ mask,
                   const float* __restrict__ t0v,
                   const float* __restrict__ t1v,
                   const float* __restrict__ mu_raw,
                   const float* __restrict__ alpha_raw,
                   const float* __restrict__ beta_raw,
                   float* __restrict__ out,
                   int N) {
    const int b    = blockIdx.x;
    const int tid  = threadIdx.x;
    const int lane = tid & 31;
    const int warp = tid >> 5;

    const float mu    = softplus_fast(mu_raw[0]);
    const float alpha = softplus_fast(alpha_raw[0]);
    const float beta  = softplus_fast(beta_raw[0]);
    const float T1    = t1v[b];

    const float* t = et   + (size_t)b * N;
    const float* m = mask + (size_t)b * N;

    __shared__ float sG[NW], sH[NW];
    __shared__ float rC[NW], rM[NW], rL[NW];

    const int base = tid * CHUNK;

    // Coalesced vector loads (2x float4 each for t and m).
    const float4 ta = *reinterpret_cast<const float4*>(t + base);
    const float4 tb = *reinterpret_cast<const float4*>(t + base + 4);
    const float4 ma = *reinterpret_cast<const float4*>(m + base);
    const float4 mb = *reinterpret_cast<const float4*>(m + base + 4);
    const float tprev = (tid == 0) ? ta.x : t[base - 1];

    float tv[CHUNK] = {ta.x, ta.y, ta.z, ta.w, tb.x, tb.y, tb.z, tb.w};
    float mv[CHUNK] = {ma.x, ma.y, ma.z, ma.w, mb.x, mb.y, mb.z, mb.w};

    // Per-element decay factors (8 independent MUFU exps).
    float e[CHUNK];
    e[0] = (tid == 0) ? 0.0f : __expf(-beta * (tv[0] - tprev));
    #pragma unroll
    for (int k = 1; k < CHUNK; k++) e[k] = __expf(-beta * (tv[k] - tv[k - 1]));

    // Chunk-local affine transform (A_out = G*A_in + H).
    float H = e[0];
    #pragma unroll
    for (int k = 1; k < CHUNK; k++) H = fmaf(e[k], H, e[k]);
    float G = ((e[0] * e[1]) * (e[2] * e[3])) * ((e[4] * e[5]) * (e[6] * e[7]));

    // ---- Independent work first: compensator + mask partials, warp-reduced
    // (fills the pipeline while the scan's shuffle chain runs).
    float acc_comp = 0.0f, acc_m = 0.0f;
    #pragma unroll
    for (int k = 0; k < CHUNK; k++) {
        acc_comp += __expf(fmaf(-beta * (T1 - tv[k]), mv[k], (1.0f - mv[k]) * (-1e20f)));
        acc_m    += mv[k];
    }

    // Inclusive warp scan over (G,H): compose(cur, prev) = (Gc*Gp, Gc*Hp+Hc),
    // interleaved with the comp/mask warp reductions for ILP.
    #pragma unroll
    for (int off = 1; off < 32; off <<= 1) {
        float Gp = __shfl_up_sync(0xffffffffu, G, off);
        float Hp = __shfl_up_sync(0xffffffffu, H, off);
        acc_comp += __shfl_xor_sync(0xffffffffu, acc_comp, off);
        acc_m    += __shfl_xor_sync(0xffffffffu, acc_m,    off);
        if (lane >= off) { H = fmaf(G, Hp, H); G *= Gp; }
    }
    float Gex = __shfl_up_sync(0xffffffffu, G, 1);   // lane-exclusive
    float Hex = __shfl_up_sync(0xffffffffu, H, 1);
    if (lane == 0) { Gex = 1.0f; Hex = 0.0f; }

    if (lane == 31) { sG[warp] = G; sH[warp] = H; }
    if (lane == 0)  { rC[warp] = acc_comp; rM[warp] = acc_m; }
    __syncthreads();                                            // BAR 1

    // warp0: 16-wide scan of warp aggregates + 16-wide reduce of comp/mask.
    float totC = 0.0f, totM = 0.0f;     // live in warp0 registers only
    if (warp == 0) {
        float g = (lane < NW) ? sG[lane] : 1.0f;
        float h = (lane < NW) ? sH[lane] : 0.0f;
        float c = (lane < NW) ? rC[lane] : 0.0f;
        float q = (lane < NW) ? rM[lane] : 0.0f;
        #pragma unroll
        for (int off = 1; off < NW; off <<= 1) {
            float gp = __shfl_up_sync(0xffffffffu, g, off);
            float hp = __shfl_up_sync(0xffffffffu, h, off);
            c += __shfl_xor_sync(0xffffffffu, c, off);
            q += __shfl_xor_sync(0xffffffffu, q, off);
            if (lane >= off) { h = fmaf(g, hp, h); g *= gp; }
        }
        sH[lane & (NW - 1)] = h;         // inclusive warp prefixes
        totC = c; totM = q;
    }
    __syncthreads();                                            // BAR 2

    // Incoming state for this thread's chunk.
    const float Aw   = (warp == 0) ? 0.0f : sH[warp - 1];
    const float A_in = fmaf(Gex, Aw, Hex);

    // Replay with true incoming state; single log of the lambda product.
    const float ab = alpha * beta;
    float A = A_in, P = 1.0f;
    #pragma unroll
    for (int k = 0; k < CHUNK; k++) {
        A = fmaf(e[k], A, e[k]);
        const float lamb = fmaf(A, ab, mu) + 1e-8f;
        P *= fmaf(mv[k], lamb - 1.0f, 1.0f);   // lamb^m for m in {0,1}
    }
    float acc_log = __logf(P);

    #pragma unroll
    for (int off = 16; off > 0; off >>= 1)
        acc_log += __shfl_xor_sync(0xffffffffu, acc_log, off);
    if (lane == 0) rL[warp] = acc_log;
    __syncthreads();                                            // BAR 3

    if (warp == 0) {
        float v = (lane < NW) ? rL[lane] : 0.0f;
        #pragma unroll
        for (int off = 1; off < NW; off <<= 1)
            v += __shfl_xor_sync(0xffffffffu, v, off);
        if (lane == 0) {
            const float T0 = t0v[b];
            const float compensator = (T1 - T0) * mu - alpha * (totC - totM);
            out[b] = v - compensator;
        }
    }
}

extern "C" void kernel_launch(void* const* d_in, const int* in_sizes, int n_in,
                              void* d_out, int out_size) {
    const float* event_times = (const float*)d_in[0];
    const float* input_mask  = (const float*)d_in[1];
    const float* t0          = (const float*)d_in[2];
    const float* t1          = (const float*)d_in[3];
    const float* mu          = (const float*)d_in[4];
    const float* alpha       = (const float*)d_in[5];
    const float* beta        = (const float*)d_in[6];
    float* out = (float*)d_out;

    const int B = in_sizes[2];      // t0 has B elements
    const int N = in_sizes[0] / B;  // 4096

    hawkes_kernel<<<B, NT>>>(event_times, input_mask, t0, t1,
                             mu, alpha, beta, out, N);
}